// round 9
// baseline (speedup 1.0000x reference)
#include <cuda_runtime.h>
#include <cuda_fp16.h>

// retinex_synthesis: out = clip(expm1(log1p(ins) + blur(log1p(bg) - log1p(ins))), 0, 1)
// blur = depthwise 31x31 Gaussian (sigma=5), separable.
// Algebra:  blur(bg_log)-blur(ins_log) = blur(d2), d2 = log2(1+bg)-log2(1+ins)
//           out = (1+ins) * 2^blur(d2) - 1
// K1: horizontal 31-tap on d2 -> fp16 temp. bg streamed (__ldcs); ins plain
//     (stays L2-resident for K2). At streaming BW ceiling (~4.9 TB/s).
// K2: vertical 31-tap, scalar FFMA-imm, 16 rows/thread (regs<=51, occ~62%).

static constexpr int Wd    = 512;
static constexpr int Hd    = 512;
static constexpr int NIMG  = 48;                // B*C = 16*3
static constexpr int NPIX  = NIMG * Hd * Wd;    // 12,582,912
static constexpr int NROWS = NIMG * Hd;         // 24,576

__device__ __half g_temp[NPIX];                 // 25.2 MB scratch (L2-resident)

// Normalized 1D Gaussian, sigma=5, 31 taps (double-derived literals -> FFMA-imm).
#define GW_LIST { \
    8.8805900e-4f, 1.5860940e-3f, 2.7217700e-3f, 4.4874400e-3f, 7.1084370e-3f, \
    1.0818768e-2f, 1.5820117e-2f, 2.2226435e-2f, 3.0002550e-2f, 3.8911210e-2f, \
    4.8486353e-2f, 5.8048703e-2f, 6.6771903e-2f, 7.3794366e-2f, 7.8357554e-2f, \
    7.9940482e-2f, \
    7.8357554e-2f, 7.3794366e-2f, 6.6771903e-2f, 5.8048703e-2f, 4.8486353e-2f, \
    3.8911210e-2f, 3.0002550e-2f, 2.2226435e-2f, 1.5820117e-2f, 1.0818768e-2f, \
    7.1084370e-3f, 4.4874400e-3f, 2.7217700e-3f, 1.5860940e-3f, 8.8805900e-4f }

__device__ __forceinline__ float ex2(float x) {        // MUFU.EX2
    float r; asm("ex2.approx.ftz.f32 %0, %1;" : "=f"(r) : "f"(x)); return r;
}
__device__ __forceinline__ float dlog2(float b, float i) {   // log2(1+b)-log2(1+i)
    return __log2f(1.0f + b) - __log2f(1.0f + i);
}
__device__ __forceinline__ unsigned h2u(__half2 h) {
    union { __half2 h; unsigned u; } c; c.h = h; return c.u;
}

// ---------------------------------------------------------------------------
// K1: horizontal blur of d2. One block = 4 rows (2048 floats).
// Thread t loads float4 #t and #(t+256) -> warp covers 512B/LDG (100% sectors).
// ---------------------------------------------------------------------------
__global__ void __launch_bounds__(256) k_hblur(const float* __restrict__ bg,
                                               const float* __restrict__ ins) {
    const float w[31] = GW_LIST;
    __shared__ __align__(16) float s[4][544];   // [0..15]=0 | data | [528..543]=0

    const int tid = threadIdx.x;
    if (tid < 128) {
        const int r = tid >> 5, p = tid & 31;
        s[r][(p < 16) ? p : (512 + p)] = 0.0f;
    }

    const size_t gb = (size_t)blockIdx.x * 512;         // float4 units
    const float4* bg4 = (const float4*)bg;
    const float4* in4 = (const float4*)ins;

#pragma unroll
    for (int h = 0; h < 2; h++) {
        const int q = tid + h * 256;                    // f4 idx in block: 0..511
        const float4 b = __ldcs(bg4 + gb + q);          // bg: stream, evict-first
        const float4 i = in4[gb + q];                   // ins: keep in L2 for K2
        const int row = q >> 7, col = (q & 127) * 4;
        *(float4*)&s[row][16 + col] =
            make_float4(dlog2(b.x, i.x), dlog2(b.y, i.y),
                        dlog2(b.z, i.z), dlog2(b.w, i.w));
    }
    __syncthreads();

    const int row = tid >> 6;             // 0..3
    const int col = (tid & 63) * 8;       // 0..504

    float v[40];
#pragma unroll
    for (int q = 0; q < 10; q++) {
        const float4 t = *(const float4*)&s[row][col + 4 * q];     // LDS.128
        v[4*q + 0] = t.x; v[4*q + 1] = t.y; v[4*q + 2] = t.z; v[4*q + 3] = t.w;
    }

    float acc[8];
#pragma unroll
    for (int r = 0; r < 8; r++) acc[r] = 0.0f;
#pragma unroll
    for (int j = 1; j < 39; j++) {
#pragma unroll
        for (int r = 0; r < 8; r++) {
            const int k = j - 1 - r;
            if (k >= 0 && k < 31) acc[r] = fmaf(w[k], v[j], acc[r]);
        }
    }

    uint4 u;
    u.x = h2u(__floats2half2_rn(acc[0], acc[1]));
    u.y = h2u(__floats2half2_rn(acc[2], acc[3]));
    u.z = h2u(__floats2half2_rn(acc[4], acc[5]));
    u.w = h2u(__floats2half2_rn(acc[6], acc[7]));
    *(uint4*)(g_temp + ((size_t)blockIdx.x * 4 + row) * Wd + col) = u;
}

// ---------------------------------------------------------------------------
// K2: vertical blur + fused epilogue. Thread = one column x, 16 row outputs.
// Scalar FFMA with immediate weights (rt_SMSP=1). GUARD only on edge y-tiles.
// ---------------------------------------------------------------------------
template <bool GUARD>
__device__ __forceinline__ void vbody(const float* __restrict__ ins,
                                      float* __restrict__ out,
                                      int y0, size_t base) {
    const float w[31] = GW_LIST;
    float acc[16];
#pragma unroll
    for (int r = 0; r < 16; r++) acc[r] = 0.0f;

#pragma unroll
    for (int m = 0; m < 46; m++) {
        const int yy = y0 + m - 15;
        float v;
        if (GUARD) v = (yy >= 0 && yy < Hd)
                     ? __half2float(g_temp[base + (size_t)yy * Wd]) : 0.0f;
        else       v = __half2float(g_temp[base + (size_t)yy * Wd]);
#pragma unroll
        for (int r = 0; r < 16; r++) {
            const int k = m - r;
            if (k >= 0 && k < 31) acc[r] = fmaf(w[k], v, acc[r]);
        }
    }

#pragma unroll
    for (int r = 0; r < 16; r++) {
        const float iv = ins[base + (size_t)(y0 + r) * Wd];      // plain LDG (L2 hit)
        const float e  = fmaf(iv + 1.0f, ex2(acc[r]), -1.0f);    // (1+ins)*2^acc - 1
        out[base + (size_t)(y0 + r) * Wd] = fminf(fmaxf(e, 0.0f), 1.0f);
    }
}

__global__ void __launch_bounds__(256, 5) k_vfinal(const float* __restrict__ ins,
                                                   float* __restrict__ out) {
    const int x  = blockIdx.x * 256 + threadIdx.x;
    const int y0 = blockIdx.y * 16;
    const size_t base = (size_t)blockIdx.z * (Hd * Wd) + x;

    if (blockIdx.y == 0 || blockIdx.y == gridDim.y - 1)
        vbody<true >(ins, out, y0, base);
    else
        vbody<false>(ins, out, y0, base);
}

// ---------------------------------------------------------------------------
extern "C" void kernel_launch(void* const* d_in, const int* in_sizes, int n_in,
                              void* d_out, int out_size) {
    (void)in_sizes; (void)n_in; (void)out_size;
    const float* bg  = (const float*)d_in[0];   // background
    const float* ins = (const float*)d_in[1];   // insatance
    float* out = (float*)d_out;

    k_hblur <<<NROWS / 4, 256>>>(bg, ins);
    k_vfinal<<<dim3(Wd / 256, Hd / 16, NIMG), 256>>>(ins, out);
}

// round 10
// speedup vs baseline: 1.0521x; 1.0521x over previous
#include <cuda_runtime.h>
#include <cuda_fp16.h>

// retinex_synthesis: out = clip(expm1(log1p(ins) + blur(log1p(bg) - log1p(ins))), 0, 1)
// blur = depthwise 31x31 Gaussian (sigma=5), separable.
// Algebra:  blur(bg_log)-blur(ins_log) = blur(d2), d2 = log2(1+bg)-log2(1+ins)
//           out = (1+ins) * 2^blur(d2) - 1
// K1: horizontal 31-tap on d2 -> fp16 temp (column pairs = half2 lanes).
//     bg streamed (__ldcs); ins plain (L2-resident for K2). At DRAM floor.
// K2: vertical 31-tap in HFMA2 (2 cols/slot: halves issue slots; kernel is
//     issue-bound at ~68%), 2 cols x 16 rows/thread, float2 fused epilogue.

static constexpr int Wd    = 512;
static constexpr int Hd    = 512;
static constexpr int NIMG  = 48;                // B*C = 16*3
static constexpr int NPIX  = NIMG * Hd * Wd;    // 12,582,912
static constexpr int NROWS = NIMG * Hd;         // 24,576

__device__ __align__(16) __half2 g_temp2[NPIX / 2];   // 25.2 MB scratch, half2-packed

// Normalized 1D Gaussian, sigma=5, 31 taps (double-derived literals).
#define GW_LIST { \
    8.8805900e-4f, 1.5860940e-3f, 2.7217700e-3f, 4.4874400e-3f, 7.1084370e-3f, \
    1.0818768e-2f, 1.5820117e-2f, 2.2226435e-2f, 3.0002550e-2f, 3.8911210e-2f, \
    4.8486353e-2f, 5.8048703e-2f, 6.6771903e-2f, 7.3794366e-2f, 7.8357554e-2f, \
    7.9940482e-2f, \
    7.8357554e-2f, 7.3794366e-2f, 6.6771903e-2f, 5.8048703e-2f, 4.8486353e-2f, \
    3.8911210e-2f, 3.0002550e-2f, 2.2226435e-2f, 1.5820117e-2f, 1.0818768e-2f, \
    7.1084370e-3f, 4.4874400e-3f, 2.7217700e-3f, 1.5860940e-3f, 8.8805900e-4f }

__device__ __forceinline__ float ex2(float x) {        // MUFU.EX2
    float r; asm("ex2.approx.ftz.f32 %0, %1;" : "=f"(r) : "f"(x)); return r;
}
__device__ __forceinline__ float dlog2(float b, float i) {   // log2(1+b)-log2(1+i)
    return __log2f(1.0f + b) - __log2f(1.0f + i);
}
__device__ __forceinline__ unsigned h2u(__half2 h) {
    union { __half2 h; unsigned u; } c; c.h = h; return c.u;
}

// ---------------------------------------------------------------------------
// K1: horizontal blur of d2. One block = 4 rows (2048 floats). UNCHANGED (at
// DRAM floor). Output uint4 = 8 consecutive-column halves = 4 half2 pairs.
// ---------------------------------------------------------------------------
__global__ void __launch_bounds__(256) k_hblur(const float* __restrict__ bg,
                                               const float* __restrict__ ins) {
    const float w[31] = GW_LIST;
    __shared__ __align__(16) float s[4][544];   // [0..15]=0 | data | [528..543]=0

    const int tid = threadIdx.x;
    if (tid < 128) {
        const int r = tid >> 5, p = tid & 31;
        s[r][(p < 16) ? p : (512 + p)] = 0.0f;
    }

    const size_t gb = (size_t)blockIdx.x * 512;         // float4 units
    const float4* bg4 = (const float4*)bg;
    const float4* in4 = (const float4*)ins;

#pragma unroll
    for (int h = 0; h < 2; h++) {
        const int q = tid + h * 256;                    // f4 idx in block: 0..511
        const float4 b = __ldcs(bg4 + gb + q);          // bg: stream, evict-first
        const float4 i = in4[gb + q];                   // ins: keep in L2 for K2
        const int row = q >> 7, col = (q & 127) * 4;
        *(float4*)&s[row][16 + col] =
            make_float4(dlog2(b.x, i.x), dlog2(b.y, i.y),
                        dlog2(b.z, i.z), dlog2(b.w, i.w));
    }
    __syncthreads();

    const int row = tid >> 6;             // 0..3
    const int col = (tid & 63) * 8;       // 0..504

    float v[40];
#pragma unroll
    for (int q = 0; q < 10; q++) {
        const float4 t = *(const float4*)&s[row][col + 4 * q];     // LDS.128
        v[4*q + 0] = t.x; v[4*q + 1] = t.y; v[4*q + 2] = t.z; v[4*q + 3] = t.w;
    }

    float acc[8];
#pragma unroll
    for (int r = 0; r < 8; r++) acc[r] = 0.0f;
#pragma unroll
    for (int j = 1; j < 39; j++) {
#pragma unroll
        for (int r = 0; r < 8; r++) {
            const int k = j - 1 - r;
            if (k >= 0 && k < 31) acc[r] = fmaf(w[k], v[j], acc[r]);
        }
    }

    uint4 u;
    u.x = h2u(__floats2half2_rn(acc[0], acc[1]));
    u.y = h2u(__floats2half2_rn(acc[2], acc[3]));
    u.z = h2u(__floats2half2_rn(acc[4], acc[5]));
    u.w = h2u(__floats2half2_rn(acc[6], acc[7]));
    *(uint4*)((__half*)g_temp2 + ((size_t)blockIdx.x * 4 + row) * Wd + col) = u;
}

// ---------------------------------------------------------------------------
// K2: vertical blur + fused epilogue. Thread = 2 adjacent columns x 16 rows.
// HFMA2 with broadcast fp16 weights: one issue slot = 2 FMAs. Temp loads are
// half2 LDG.32 (no convert). GUARD only on edge y-tiles.
// Block 256 threads = full 512-col width; grid = (Hd/16, NIMG).
// ---------------------------------------------------------------------------
template <bool GUARD>
__device__ __forceinline__ void vbody(const float2* __restrict__ ins2,
                                      float2* __restrict__ out2,
                                      int y0, size_t base) {
    const float w[31] = GW_LIST;

    __half2 acc[16];
#pragma unroll
    for (int r = 0; r < 16; r++) acc[r] = __half2half2(__ushort_as_half(0));

#pragma unroll
    for (int m = 0; m < 46; m++) {
        const int yy = y0 + m - 15;
        __half2 v;
        if (GUARD && (yy < 0 || yy >= Hd)) v = __half2half2(__ushort_as_half(0));
        else                               v = g_temp2[base + (size_t)yy * 256];
#pragma unroll
        for (int r = 0; r < 16; r++) {
            const int k = m - r;
            if (k >= 0 && k < 31)
                acc[r] = __hfma2(v, __floats2half2_rn(w[k], w[k]), acc[r]);
        }
    }

#pragma unroll
    for (int r = 0; r < 16; r++) {
        const float2 a  = __half22float2(acc[r]);
        const float2 iv = ins2[base + (size_t)(y0 + r) * 256];   // plain LDG (L2)
        const float e0 = fmaf(iv.x + 1.0f, ex2(a.x), -1.0f);     // (1+ins)*2^acc-1
        const float e1 = fmaf(iv.y + 1.0f, ex2(a.y), -1.0f);
        float2 o;
        o.x = fminf(fmaxf(e0, 0.0f), 1.0f);
        o.y = fminf(fmaxf(e1, 0.0f), 1.0f);
        out2[base + (size_t)(y0 + r) * 256] = o;
    }
}

__global__ void __launch_bounds__(256, 4) k_vfinal(const float2* __restrict__ ins2,
                                                   float2* __restrict__ out2) {
    const int y0 = blockIdx.x * 16;
    const size_t base = (size_t)blockIdx.y * (Hd * 256) + threadIdx.x;

    if (blockIdx.x == 0 || blockIdx.x == gridDim.x - 1)
        vbody<true >(ins2, out2, y0, base);
    else
        vbody<false>(ins2, out2, y0, base);
}

// ---------------------------------------------------------------------------
extern "C" void kernel_launch(void* const* d_in, const int* in_sizes, int n_in,
                              void* d_out, int out_size) {
    (void)in_sizes; (void)n_in; (void)out_size;
    const float* bg  = (const float*)d_in[0];   // background
    const float* ins = (const float*)d_in[1];   // insatance
    float* out = (float*)d_out;

    k_hblur <<<NROWS / 4, 256>>>(bg, ins);
    k_vfinal<<<dim3(Hd / 16, NIMG), 256>>>((const float2*)ins, (float2*)out);
}